// round 5
// baseline (speedup 1.0000x reference)
#include <cuda_runtime.h>
#include <cuda_bf16.h>
#include <cstdint>
#include <cmath>

// Problem: B=64, T=512, E=256, U=256, bidirectional LSTM (all-tanh), mask carry.

// ---------------------------------------------------------------------------
// Device scratch
// ---------------------------------------------------------------------------
__device__ float g_Z[2ull * 512 * 64 * 1024];                  // [dir][t][b][u*4+g]
__device__ unsigned char g_mask[64 * 512];                     // [b][t]
__device__ __align__(16) __nv_bfloat16 g_Xhi[32768ull * 256];  // [m=t*64+b][k]
__device__ __align__(16) __nv_bfloat16 g_Xlo[32768ull * 256];
__device__ __align__(16) __nv_bfloat16 g_Whi[2ull * 1024 * 256]; // [dir][q=u*4+g][k]
__device__ __align__(16) __nv_bfloat16 g_Wlo[2ull * 1024 * 256];

// ---------------------------------------------------------------------------
// Small PTX helpers (family-level features only)
// ---------------------------------------------------------------------------
__device__ __forceinline__ uint32_t smem_u32(const void* p)
{
    uint32_t a;
    asm("{ .reg .u64 t; cvta.to.shared.u64 t, %1; cvt.u32.u64 %0, t; }"
        : "=r"(a) : "l"(p));
    return a;
}

#define CP_ASYNC16(dst, src) \
    asm volatile("cp.async.cg.shared.global [%0], [%1], 16;" \
                 :: "r"(dst), "l"(src) : "memory")
#define CP_ASYNC_COMMIT() asm volatile("cp.async.commit_group;" ::: "memory")
#define CP_ASYNC_WAIT(n)  asm volatile("cp.async.wait_group %0;" :: "n"(n) : "memory")

__device__ __forceinline__ void ldm4(uint32_t* r, uint32_t addr)
{
    asm volatile("ldmatrix.sync.aligned.m8n8.x4.shared.b16 {%0,%1,%2,%3}, [%4];"
                 : "=r"(r[0]), "=r"(r[1]), "=r"(r[2]), "=r"(r[3]) : "r"(addr));
}

__device__ __forceinline__ void mma16816(float* c, const uint32_t* a,
                                         uint32_t b0, uint32_t b1)
{
    asm volatile(
        "mma.sync.aligned.m16n8k16.row.col.f32.bf16.bf16.f32 "
        "{%0,%1,%2,%3}, {%4,%5,%6,%7}, {%8,%9}, {%0,%1,%2,%3};"
        : "+f"(c[0]), "+f"(c[1]), "+f"(c[2]), "+f"(c[3])
        : "r"(a[0]), "r"(a[1]), "r"(a[2]), "r"(a[3]), "r"(b0), "r"(b1));
}

__device__ __forceinline__ uint64_t packf2(float a, float b)
{
    uint64_t r;
    asm("mov.b64 %0, {%1, %2};" : "=l"(r) : "f"(a), "f"(b));
    return r;
}
__device__ __forceinline__ uint64_t fmaf2(uint64_t a, uint64_t b, uint64_t c)
{
    uint64_t d;
    asm("fma.rn.f32x2 %0, %1, %2, %3;" : "=l"(d) : "l"(a), "l"(b), "l"(c));
    return d;
}
__device__ __forceinline__ uint32_t mapa_rank(uint32_t addr, uint32_t rank)
{
    uint32_t r;
    asm("mapa.shared::cluster.u32 %0, %1, %2;" : "=r"(r) : "r"(addr), "r"(rank));
    return r;
}
__device__ __forceinline__ void st_cluster_f32(uint32_t addr, float v)
{
    asm volatile("st.shared::cluster.f32 [%0], %1;" :: "r"(addr), "f"(v) : "memory");
}
#define CLUSTER_SYNC() do { \
    asm volatile("barrier.cluster.arrive.aligned;" ::: "memory"); \
    asm volatile("barrier.cluster.wait.aligned;"   ::: "memory"); \
} while (0)

// ---------------------------------------------------------------------------
// Mask kernel: mask[b][t] = any(x[b,t,:] != 0)
// ---------------------------------------------------------------------------
__global__ void mask_kernel(const float* __restrict__ x)
{
    int gw   = (blockIdx.x * blockDim.x + threadIdx.x) >> 5;
    int lane = threadIdx.x & 31;
    if (gw >= 64 * 512) return;
    const float4* p = reinterpret_cast<const float4*>(x + (size_t)gw * 256);
    float4 a = p[lane];
    float4 b = p[lane + 32];
    bool nz = (a.x != 0.f) || (a.y != 0.f) || (a.z != 0.f) || (a.w != 0.f) ||
              (b.x != 0.f) || (b.y != 0.f) || (b.z != 0.f) || (b.w != 0.f);
    unsigned m = __ballot_sync(0xffffffffu, nz);
    if (lane == 0) g_mask[gw] = (m != 0u) ? 1 : 0;
}

// ---------------------------------------------------------------------------
// Converters: fp32 -> (hi, lo) bf16 split
// ---------------------------------------------------------------------------
__device__ __forceinline__ void split_bf16(float f, __nv_bfloat16& hi, __nv_bfloat16& lo)
{
    hi = __float2bfloat16_rn(f);
    lo = __float2bfloat16_rn(f - __bfloat162float(hi));
}

__global__ __launch_bounds__(256) void convert_x_kernel(const float* __restrict__ x)
{
    uint32_t idx = blockIdx.x * 256u + threadIdx.x;   // 2,097,152 total
    int m = idx >> 6, q = idx & 63;
    int b = m & 63, t = m >> 6;
    float4 v = *reinterpret_cast<const float4*>(x + ((size_t)b * 512 + t) * 256 + q * 4);
    __nv_bfloat16 h0, h1, h2, h3, l0, l1, l2, l3;
    split_bf16(v.x, h0, l0);
    split_bf16(v.y, h1, l1);
    split_bf16(v.z, h2, l2);
    split_bf16(v.w, h3, l3);
    __nv_bfloat162 hp0(h0, h1), hp1(h2, h3), lp0(l0, l1), lp1(l2, l3);
    uint2 hv, lv;
    hv.x = *reinterpret_cast<uint32_t*>(&hp0);
    hv.y = *reinterpret_cast<uint32_t*>(&hp1);
    lv.x = *reinterpret_cast<uint32_t*>(&lp0);
    lv.y = *reinterpret_cast<uint32_t*>(&lp1);
    *reinterpret_cast<uint2*>(g_Xhi + (size_t)m * 256 + q * 4) = hv;
    *reinterpret_cast<uint2*>(g_Xlo + (size_t)m * 256 + q * 4) = lv;
}

__global__ __launch_bounds__(256) void convert_w_kernel(
    const float* __restrict__ Wk_f, const float* __restrict__ Wk_b)
{
    uint32_t idx = blockIdx.x * 256u + threadIdx.x;   // 524,288 total
    int dir = idx >> 18;
    uint32_t rem = idx & 0x3FFFFu;
    int q = rem >> 8, k = rem & 255;
    int u = q >> 2, g = q & 3;
    float v = (dir ? Wk_b : Wk_f)[k * 1024 + g * 256 + u];
    __nv_bfloat16 hi, lo;
    split_bf16(v, hi, lo);
    g_Whi[idx] = hi;
    g_Wlo[idx] = lo;
}

// ---------------------------------------------------------------------------
// Input GEMM via mma.sync bf16 split-3 (unchanged: 255us, tensor 67%)
// ---------------------------------------------------------------------------
#define GEMM_STAGE_BYTES 65536
#define GEMM_SMEM_BYTES  (2 * GEMM_STAGE_BYTES + 1024)

__global__ __launch_bounds__(256, 1) void gemm_mma_kernel(
    const float* __restrict__ b_f, const float* __restrict__ b_b)
{
    extern __shared__ char smc[];
    char* stages = smc;
    float* bias_s = reinterpret_cast<float*>(smc + 2 * GEMM_STAGE_BYTES);
    const uint32_t st_u32 = smem_u32(stages);

    const int tid  = threadIdx.x;
    const int wid  = tid >> 5, lane = tid & 31;
    const int wm   = wid & 3, wn = wid >> 2;
    const int mt   = blockIdx.x * 128;
    const int nt   = blockIdx.y;
    const int dir  = nt >> 3;
    const int q0   = (nt & 7) * 128;

    if (tid < 128) {
        const int q = q0 + tid;
        bias_s[tid] = (dir ? b_b : b_f)[(q & 3) * 256 + (q >> 2)];
    }

    const char* srcs[4] = {
        reinterpret_cast<const char*>(g_Xhi),
        reinterpret_cast<const char*>(g_Xlo),
        reinterpret_cast<const char*>(g_Whi),
        reinterpret_cast<const char*>(g_Wlo)
    };

    auto load_chunk = [&](int c, int s) {
        const uint32_t sb = st_u32 + (uint32_t)s * GEMM_STAGE_BYTES;
        const int koff = c * 128;
#pragma unroll
        for (int it = 0; it < 16; it++) {
            const int idx    = it * 256 + tid;
            const int region = idx >> 10;
            const int r      = (idx >> 3) & 127;
            const int q4     = idx & 7;
            const int grow   = (region < 2) ? (mt + r) : (dir * 1024 + q0 + r);
            const char* src  = srcs[region] + (size_t)grow * 512 + koff + q4 * 16;
            const uint32_t dst = sb + region * 16384 + r * 128
                               + (((uint32_t)q4 * 16) ^ (((uint32_t)(r & 7)) * 16));
            CP_ASYNC16(dst, src);
        }
    };

    const int grp = lane >> 3, lr = lane & 7;
    const uint32_t xr16 = (uint32_t)lr * 16;
    const uint32_t koffA = (uint32_t)(grp >> 1) * 16;
    const uint32_t koffB = (uint32_t)(grp & 1) * 16;
    uint32_t baseA[2], baseB[4];
#pragma unroll
    for (int i = 0; i < 2; i++) {
        const int rowA = wm * 32 + i * 16 + lr + (grp & 1) * 8;
        baseA[i] = (uint32_t)rowA * 128;
    }
#pragma unroll
    for (int j2 = 0; j2 < 4; j2++) {
        const int rowB = wn * 64 + j2 * 16 + lr + (grp >> 1) * 8;
        baseB[j2] = (uint32_t)rowB * 128;
    }

    float acc[2][8][4];
#pragma unroll
    for (int i = 0; i < 2; i++)
#pragma unroll
        for (int j = 0; j < 8; j++)
#pragma unroll
            for (int v = 0; v < 4; v++) acc[i][j][v] = 0.f;

    load_chunk(0, 0);
    CP_ASYNC_COMMIT();

#pragma unroll
    for (int c = 0; c < 4; c++) {
        if (c < 3) { load_chunk(c + 1, (c + 1) & 1); CP_ASYNC_COMMIT(); }
        if (c < 3) CP_ASYNC_WAIT(1); else CP_ASYNC_WAIT(0);
        __syncthreads();

        const uint32_t sb = st_u32 + (uint32_t)(c & 1) * GEMM_STAGE_BYTES;
        const uint32_t Ah = sb, Al = sb + 16384, Bh = sb + 32768, Bl = sb + 49152;

#pragma unroll
        for (int ks = 0; ks < 4; ks++) {
            const uint32_t offA = (((uint32_t)ks * 32) + koffA) ^ xr16;
            const uint32_t offB = (((uint32_t)ks * 32) + koffB) ^ xr16;
            uint32_t ah[2][4], al[2][4], bh[4][4], bl[4][4];
#pragma unroll
            for (int i = 0; i < 2; i++) {
                ldm4(ah[i], Ah + baseA[i] + offA);
                ldm4(al[i], Al + baseA[i] + offA);
            }
#pragma unroll
            for (int j2 = 0; j2 < 4; j2++) {
                ldm4(bh[j2], Bh + baseB[j2] + offB);
                ldm4(bl[j2], Bl + baseB[j2] + offB);
            }
#pragma unroll
            for (int i = 0; i < 2; i++)
#pragma unroll
                for (int j = 0; j < 8; j++) {
                    const int j2 = j >> 1, sel = (j & 1) * 2;
                    mma16816(acc[i][j], ah[i], bh[j2][sel], bh[j2][sel + 1]);
                    mma16816(acc[i][j], ah[i], bl[j2][sel], bl[j2][sel + 1]);
                    mma16816(acc[i][j], al[i], bh[j2][sel], bh[j2][sel + 1]);
                }
        }
        __syncthreads();
    }

    const int mrow0 = mt + wm * 32 + (lane >> 2);
    const int qcol0 = q0 + wn * 64 + (lane & 3) * 2;
#pragma unroll
    for (int i = 0; i < 2; i++) {
#pragma unroll
        for (int j = 0; j < 8; j++) {
            const int q  = qcol0 + j * 8;
            const float bx = bias_s[q - q0], by = bias_s[q - q0 + 1];
#pragma unroll
            for (int half = 0; half < 2; half++) {
                const int m  = mrow0 + i * 16 + half * 8;
                const int bb = m & 63, tt = m >> 6;
                float2 v;
                v.x = acc[i][j][half * 2 + 0] + bx;
                v.y = acc[i][j][half * 2 + 1] + by;
                *reinterpret_cast<float2*>(
                    g_Z + (((size_t)dir * 512 + tt) * 64 + bb) * 1024 + q) = v;
            }
        }
    }
}

// ---------------------------------------------------------------------------
// Recurrence v3 — dense-LDS split-k, conflict-free partial exchange.
// 128 CTAs = 2 dirs x 8 batch-groups x 8 cluster ranks (cluster of 8).
// SMEM floats: Wr_s[256 k][128 col]            (32768)  col = u_local*4 + gate
//              h_T [2][256 u][8 b]              (4096)
//              part4[(2 j2 * 8 w * 4 bp) rows]  rows stride 33 float4 (8448 f)
//              mask bytes [8][512]              (4096 B)
// GEMM phase: warp w covers k in [32w,32w+32); per k: 1 dense LDS.128 of the
// 512B weight row (lane l -> cols 4l..4l+3), 2 uniform h-pair loads, 16 FFMA2.
// Exchange: lane-dense STS.128 (part4[(j2*32 + w*4 + bp)*33 + lane]) -> no
// bank conflicts; reduce reads 16 LDS.128/thread across bank quads.
// ---------------------------------------------------------------------------
#define REC_WRS_F   32768
#define REC_HT_F    4096
#define REC_PART_F  8448
#define REC_SMEM_BYTES ((REC_WRS_F + REC_HT_F + REC_PART_F) * 4 + 4096)

__global__ void __cluster_dims__(8, 1, 1) __launch_bounds__(256, 1)
lstm_rec_kernel(const float* __restrict__ Wr_f, const float* __restrict__ Wr_b,
                float* __restrict__ out)
{
    extern __shared__ float sm[];
    float*  Wr_s = sm;
    float*  h_T  = sm + REC_WRS_F;
    float4* part4 = reinterpret_cast<float4*>(sm + REC_WRS_F + REC_HT_F);
    unsigned char* m_s =
        reinterpret_cast<unsigned char*>(sm + REC_WRS_F + REC_HT_F + REC_PART_F);

    const int tid  = threadIdx.x;
    const int bx   = blockIdx.x;
    const int dir  = bx >> 6;
    const int rank = bx & 7;
    const int bg   = (bx & 63) >> 3;
    const int w    = tid >> 5, lane = tid & 31;
    // gates-phase mapping: one thread per (b, u_local)
    const int ul   = tid >> 3;          // 0..31
    const int b    = tid & 7;           // 0..7
    const int ug   = (rank << 5) + ul;  // 0..255
    const int b_global = (bg << 3) + b;

    // --- init: Wr slice ---------------------------------------------------
    const float* Wr = dir ? Wr_b : Wr_f;
    for (int i = tid; i < 32768; i += 256) {
        const int lul = i & 31;
        const int g   = (i >> 5) & 3;
        const int k   = i >> 7;
        Wr_s[k * 128 + lul * 4 + g] = Wr[k * 1024 + g * 256 + (rank << 5) + lul];
    }
    for (int i = tid; i < 8 * 512; i += 256)
        m_s[i] = g_mask[((bg << 3) + (i >> 9)) * 512 + (i & 511)];
    for (int i = tid; i < REC_HT_F; i += 256) h_T[i] = 0.f;

    // --- DSMEM broadcast addresses (both buffers x 8 ranks) ---------------
    const uint32_t hbase = smem_u32(h_T);
    const uint32_t l0 = hbase + ((uint32_t)(ug * 8 + b) << 2);
    const uint32_t l1 = l0 + 2048 * 4;
    uint32_t r0[8], r1[8];
#pragma unroll
    for (int r = 0; r < 8; r++) { r0[r] = mapa_rank(l0, r); r1[r] = mapa_rank(l1, r); }

    CLUSTER_SYNC();

    float cst = 0.f, hlast = 0.f;
    int cur = 0;

    const float4* Z4 = reinterpret_cast<const float4*>(g_Z);
    const int t0 = dir ? 511 : 0;
    float4 znext = __ldg(&Z4[(((size_t)dir * 512 + t0) * 64 + b_global) * 256 + ug]);

    // GEMM-phase pointers (warp-based)
    const float4* wrow0 = reinterpret_cast<const float4*>(Wr_s + (w << 5) * 128) + lane;
    const int     bsel  = b & 1;
    const int     bp_t  = b >> 1;

    for (int step = 0; step < 512; step++) {
        const int t = dir ? (511 - step) : step;
        const float4 zin = znext;
        if (step < 511) {
            const int tn = dir ? (510 - step) : (step + 1);
            znext = __ldg(&Z4[(((size_t)dir * 512 + tn) * 64 + b_global) * 256 + ug]);
        }

        // ---- GEMM phase: k in [32w, 32w+32), 8 b x 4 cols per lane ------
        uint64_t acc[4][4];
#pragma unroll
        for (int i = 0; i < 4; i++)
#pragma unroll
            for (int j = 0; j < 4; j++) acc[i][j] = 0;

        const ulonglong2* hk =
            reinterpret_cast<const ulonglong2*>(h_T + cur * 2048 + (w << 5) * 8);
        const float4* wr = wrow0;

#pragma unroll 8
        for (int kk = 0; kk < 32; kk++) {
            const ulonglong2 hA = hk[kk * 2];        // (h_b0,h_b1),(h_b2,h_b3)
            const ulonglong2 hB = hk[kk * 2 + 1];    // (h_b4,h_b5),(h_b6,h_b7)
            const float4 wv = wr[kk * 32];
            uint64_t wd0 = packf2(wv.x, wv.x);
            uint64_t wd1 = packf2(wv.y, wv.y);
            uint64_t wd2 = packf2(wv.z, wv.z);
            uint64_t wd3 = packf2(wv.w, wv.w);
            acc[0][0] = fmaf2(hA.x, wd0, acc[0][0]);
            acc[0][1] = fmaf2(hA.x, wd1, acc[0][1]);
            acc[0][2] = fmaf2(hA.x, wd2, acc[0][2]);
            acc[0][3] = fmaf2(hA.x, wd3, acc[0][3]);
            acc[1][0] = fmaf2(hA.y, wd0, acc[1][0]);
            acc[1][1] = fmaf2(hA.y, wd1, acc[1][1]);
            acc[1][2] = fmaf2(hA.y, wd2, acc[1][2]);
            acc[1][3] = fmaf2(hA.y, wd3, acc[1][3]);
            acc[2][0] = fmaf2(hB.x, wd0, acc[2][0]);
            acc[2][1] = fmaf2(hB.x, wd1, acc[2][1]);
            acc[2][2] = fmaf2(hB.x, wd2, acc[2][2]);
            acc[2][3] = fmaf2(hB.x, wd3, acc[2][3]);
            acc[3][0] = fmaf2(hB.y, wd0, acc[3][0]);
            acc[3][1] = fmaf2(hB.y, wd1, acc[3][1]);
            acc[3][2] = fmaf2(hB.y, wd2, acc[3][2]);
            acc[3][3] = fmaf2(hB.y, wd3, acc[3][3]);
        }

        // ---- store partials (lane-dense, conflict-free) -----------------
        // part4[(j2*32 + w*4 + bp)*33 + lane] = [c0_be, c0_bo, c1_be, c1_bo]
#pragma unroll
        for (int bp = 0; bp < 4; bp++) {
            ulonglong2 v0, v1;
            v0.x = acc[bp][0]; v0.y = acc[bp][1];
            v1.x = acc[bp][2]; v1.y = acc[bp][3];
            *reinterpret_cast<ulonglong2*>(&part4[((w << 2) + bp) * 33 + lane]) = v0;
            *reinterpret_cast<ulonglong2*>(&part4[(32 + (w << 2) + bp) * 33 + lane]) = v1;
        }
        __syncthreads();

        // ---- reduce + gates per (b, u_local) thread ---------------------
        float z0 = zin.x, z1 = zin.y, z2 = zin.z, z3 = zin.w;
#pragma unroll
        for (int w8 = 0; w8 < 8; w8++) {
            const float4 a = part4[((w8 << 2) + bp_t) * 33 + ul];
            const float4 c = part4[(32 + (w8 << 2) + bp_t) * 33 + ul];
            z0 += bsel ? a.y : a.x;
            z1 += bsel ? a.w : a.z;
            z2 += bsel ? c.y : c.x;
            z3 += bsel ? c.w : c.z;
        }

        const float gi = tanhf(z0);
        const float gf = tanhf(z1);
        const float gc = tanhf(z2);
        const float go = tanhf(z3);
        const float cn = fmaf(gf, cst, gi * gc);
        const float hn = go * tanhf(cn);

        const bool  mk   = m_s[(b << 9) + t] != 0;
        const float hold = h_T[cur * 2048 + ug * 8 + b];
        const float hv   = mk ? hn : hold;
        cst = mk ? cn : cst;

        out[((size_t)b_global * 512 + t) * 512 + (dir << 8) + ug] = hv;
        hlast = hv;

        // broadcast h to all 8 CTAs' next buffer
        const int nxt = cur ^ 1;
#pragma unroll
        for (int r = 0; r < 8; r++)
            st_cluster_f32(nxt ? r1[r] : r0[r], hv);

        CLUSTER_SYNC();
        cur = nxt;
    }

    out[16777216 + (size_t)b_global * 512 + (dir << 8) + ug] = hlast;
}

// ---------------------------------------------------------------------------
// Launch
// ---------------------------------------------------------------------------
extern "C" void kernel_launch(void* const* d_in, const int* in_sizes, int n_in,
                              void* d_out, int out_size)
{
    const float* x    = (const float*)d_in[0];
    const float* Wk_f = (const float*)d_in[1];
    const float* Wr_f = (const float*)d_in[2];
    const float* b_f  = (const float*)d_in[3];
    const float* Wk_b = (const float*)d_in[4];
    const float* Wr_b = (const float*)d_in[5];
    const float* b_b  = (const float*)d_in[6];
    float* out = (float*)d_out;

    mask_kernel<<<4096, 256>>>(x);
    convert_x_kernel<<<8192, 256>>>(x);
    convert_w_kernel<<<2048, 256>>>(Wk_f, Wk_b);

    cudaFuncSetAttribute(gemm_mma_kernel,
                         cudaFuncAttributeMaxDynamicSharedMemorySize, GEMM_SMEM_BYTES);
    dim3 gg(256, 16);
    gemm_mma_kernel<<<gg, 256, GEMM_SMEM_BYTES>>>(b_f, b_b);

    cudaFuncSetAttribute(lstm_rec_kernel,
                         cudaFuncAttributeMaxDynamicSharedMemorySize, REC_SMEM_BYTES);
    lstm_rec_kernel<<<128, 256, REC_SMEM_BYTES>>>(Wr_f, Wr_b, out);
}

// round 6
// speedup vs baseline: 1.8118x; 1.8118x over previous
#include <cuda_runtime.h>
#include <cuda_bf16.h>
#include <cstdint>
#include <cmath>

// Problem: B=64, T=512, E=256, U=256, bidirectional LSTM (all-tanh), mask carry.

// ---------------------------------------------------------------------------
// Device scratch
// ---------------------------------------------------------------------------
__device__ float g_Z[2ull * 512 * 64 * 1024];                  // [dir][t][b][u*4+g]
__device__ unsigned char g_mask[64 * 512];                     // [b][t]
__device__ __align__(16) __nv_bfloat16 g_Xhi[32768ull * 256];  // [m=t*64+b][k]
__device__ __align__(16) __nv_bfloat16 g_Xlo[32768ull * 256];
__device__ __align__(16) __nv_bfloat16 g_Whi[2ull * 1024 * 256]; // [dir][q=u*4+g][k]
__device__ __align__(16) __nv_bfloat16 g_Wlo[2ull * 1024 * 256];

// ---------------------------------------------------------------------------
// PTX helpers (family-level features only)
// ---------------------------------------------------------------------------
__device__ __forceinline__ uint32_t smem_u32(const void* p)
{
    uint32_t a;
    asm("{ .reg .u64 t; cvta.to.shared.u64 t, %1; cvt.u32.u64 %0, t; }"
        : "=r"(a) : "l"(p));
    return a;
}

#define CP_ASYNC16(dst, src) \
    asm volatile("cp.async.cg.shared.global [%0], [%1], 16;" \
                 :: "r"(dst), "l"(src) : "memory")
#define CP_ASYNC_COMMIT() asm volatile("cp.async.commit_group;" ::: "memory")
#define CP_ASYNC_WAIT(n)  asm volatile("cp.async.wait_group %0;" :: "n"(n) : "memory")

__device__ __forceinline__ void ldm4(uint32_t* r, uint32_t addr)
{
    asm volatile("ldmatrix.sync.aligned.m8n8.x4.shared.b16 {%0,%1,%2,%3}, [%4];"
                 : "=r"(r[0]), "=r"(r[1]), "=r"(r[2]), "=r"(r[3]) : "r"(addr));
}

__device__ __forceinline__ void mma16816(float* c, const uint32_t* a,
                                         uint32_t b0, uint32_t b1)
{
    asm volatile(
        "mma.sync.aligned.m16n8k16.row.col.f32.bf16.bf16.f32 "
        "{%0,%1,%2,%3}, {%4,%5,%6,%7}, {%8,%9}, {%0,%1,%2,%3};"
        : "+f"(c[0]), "+f"(c[1]), "+f"(c[2]), "+f"(c[3])
        : "r"(a[0]), "r"(a[1]), "r"(a[2]), "r"(a[3]), "r"(b0), "r"(b1));
}

__device__ __forceinline__ uint32_t mapa_rank(uint32_t addr, uint32_t rank)
{
    uint32_t r;
    asm("mapa.shared::cluster.u32 %0, %1, %2;" : "=r"(r) : "r"(addr), "r"(rank));
    return r;
}
__device__ __forceinline__ void st_cluster_f32(uint32_t addr, float v)
{
    asm volatile("st.shared::cluster.f32 [%0], %1;" :: "r"(addr), "f"(v) : "memory");
}
#define CLUSTER_SYNC() do { \
    asm volatile("barrier.cluster.arrive.aligned;" ::: "memory"); \
    asm volatile("barrier.cluster.wait.aligned;"   ::: "memory"); \
} while (0)

// ---------------------------------------------------------------------------
// Mask kernel: mask[b][t] = any(x[b,t,:] != 0)
// ---------------------------------------------------------------------------
__global__ void mask_kernel(const float* __restrict__ x)
{
    int gw   = (blockIdx.x * blockDim.x + threadIdx.x) >> 5;
    int lane = threadIdx.x & 31;
    if (gw >= 64 * 512) return;
    const float4* p = reinterpret_cast<const float4*>(x + (size_t)gw * 256);
    float4 a = p[lane];
    float4 b = p[lane + 32];
    bool nz = (a.x != 0.f) || (a.y != 0.f) || (a.z != 0.f) || (a.w != 0.f) ||
              (b.x != 0.f) || (b.y != 0.f) || (b.z != 0.f) || (b.w != 0.f);
    unsigned m = __ballot_sync(0xffffffffu, nz);
    if (lane == 0) g_mask[gw] = (m != 0u) ? 1 : 0;
}

// ---------------------------------------------------------------------------
// Converters: fp32 -> (hi, lo) bf16 split
// ---------------------------------------------------------------------------
__device__ __forceinline__ void split_bf16(float f, __nv_bfloat16& hi, __nv_bfloat16& lo)
{
    hi = __float2bfloat16_rn(f);
    lo = __float2bfloat16_rn(f - __bfloat162float(hi));
}

__global__ __launch_bounds__(256) void convert_x_kernel(const float* __restrict__ x)
{
    uint32_t idx = blockIdx.x * 256u + threadIdx.x;   // 2,097,152 total
    int m = idx >> 6, q = idx & 63;
    int b = m & 63, t = m >> 6;
    float4 v = *reinterpret_cast<const float4*>(x + ((size_t)b * 512 + t) * 256 + q * 4);
    __nv_bfloat16 h0, h1, h2, h3, l0, l1, l2, l3;
    split_bf16(v.x, h0, l0);
    split_bf16(v.y, h1, l1);
    split_bf16(v.z, h2, l2);
    split_bf16(v.w, h3, l3);
    __nv_bfloat162 hp0(h0, h1), hp1(h2, h3), lp0(l0, l1), lp1(l2, l3);
    uint2 hv, lv;
    hv.x = *reinterpret_cast<uint32_t*>(&hp0);
    hv.y = *reinterpret_cast<uint32_t*>(&hp1);
    lv.x = *reinterpret_cast<uint32_t*>(&lp0);
    lv.y = *reinterpret_cast<uint32_t*>(&lp1);
    *reinterpret_cast<uint2*>(g_Xhi + (size_t)m * 256 + q * 4) = hv;
    *reinterpret_cast<uint2*>(g_Xlo + (size_t)m * 256 + q * 4) = lv;
}

__global__ __launch_bounds__(256) void convert_w_kernel(
    const float* __restrict__ Wk_f, const float* __restrict__ Wk_b)
{
    uint32_t idx = blockIdx.x * 256u + threadIdx.x;   // 524,288 total
    int dir = idx >> 18;
    uint32_t rem = idx & 0x3FFFFu;
    int q = rem >> 8, k = rem & 255;
    int u = q >> 2, g = q & 3;
    float v = (dir ? Wk_b : Wk_f)[k * 1024 + g * 256 + u];
    __nv_bfloat16 hi, lo;
    split_bf16(v, hi, lo);
    g_Whi[idx] = hi;
    g_Wlo[idx] = lo;
}

// ---------------------------------------------------------------------------
// Input GEMM via mma.sync bf16 split-3 (proven: ~255us, tensor 67%)
// ---------------------------------------------------------------------------
#define GEMM_STAGE_BYTES 65536
#define GEMM_SMEM_BYTES  (2 * GEMM_STAGE_BYTES + 1024)

__global__ __launch_bounds__(256, 1) void gemm_mma_kernel(
    const float* __restrict__ b_f, const float* __restrict__ b_b)
{
    extern __shared__ char smc[];
    char* stages = smc;
    float* bias_s = reinterpret_cast<float*>(smc + 2 * GEMM_STAGE_BYTES);
    const uint32_t st_u32 = smem_u32(stages);

    const int tid  = threadIdx.x;
    const int wid  = tid >> 5, lane = tid & 31;
    const int wm   = wid & 3, wn = wid >> 2;
    const int mt   = blockIdx.x * 128;
    const int nt   = blockIdx.y;
    const int dir  = nt >> 3;
    const int q0   = (nt & 7) * 128;

    if (tid < 128) {
        const int q = q0 + tid;
        bias_s[tid] = (dir ? b_b : b_f)[(q & 3) * 256 + (q >> 2)];
    }

    const char* srcs[4] = {
        reinterpret_cast<const char*>(g_Xhi),
        reinterpret_cast<const char*>(g_Xlo),
        reinterpret_cast<const char*>(g_Whi),
        reinterpret_cast<const char*>(g_Wlo)
    };

    auto load_chunk = [&](int c, int s) {
        const uint32_t sb = st_u32 + (uint32_t)s * GEMM_STAGE_BYTES;
        const int koff = c * 128;
#pragma unroll
        for (int it = 0; it < 16; it++) {
            const int idx    = it * 256 + tid;
            const int region = idx >> 10;
            const int r      = (idx >> 3) & 127;
            const int q4     = idx & 7;
            const int grow   = (region < 2) ? (mt + r) : (dir * 1024 + q0 + r);
            const char* src  = srcs[region] + (size_t)grow * 512 + koff + q4 * 16;
            const uint32_t dst = sb + region * 16384 + r * 128
                               + (((uint32_t)q4 * 16) ^ (((uint32_t)(r & 7)) * 16));
            CP_ASYNC16(dst, src);
        }
    };

    const int grp = lane >> 3, lr = lane & 7;
    const uint32_t xr16 = (uint32_t)lr * 16;
    const uint32_t koffA = (uint32_t)(grp >> 1) * 16;
    const uint32_t koffB = (uint32_t)(grp & 1) * 16;
    uint32_t baseA[2], baseB[4];
#pragma unroll
    for (int i = 0; i < 2; i++) {
        const int rowA = wm * 32 + i * 16 + lr + (grp & 1) * 8;
        baseA[i] = (uint32_t)rowA * 128;
    }
#pragma unroll
    for (int j2 = 0; j2 < 4; j2++) {
        const int rowB = wn * 64 + j2 * 16 + lr + (grp >> 1) * 8;
        baseB[j2] = (uint32_t)rowB * 128;
    }

    float acc[2][8][4];
#pragma unroll
    for (int i = 0; i < 2; i++)
#pragma unroll
        for (int j = 0; j < 8; j++)
#pragma unroll
            for (int v = 0; v < 4; v++) acc[i][j][v] = 0.f;

    load_chunk(0, 0);
    CP_ASYNC_COMMIT();

#pragma unroll
    for (int c = 0; c < 4; c++) {
        if (c < 3) { load_chunk(c + 1, (c + 1) & 1); CP_ASYNC_COMMIT(); }
        if (c < 3) CP_ASYNC_WAIT(1); else CP_ASYNC_WAIT(0);
        __syncthreads();

        const uint32_t sb = st_u32 + (uint32_t)(c & 1) * GEMM_STAGE_BYTES;
        const uint32_t Ah = sb, Al = sb + 16384, Bh = sb + 32768, Bl = sb + 49152;

#pragma unroll
        for (int ks = 0; ks < 4; ks++) {
            const uint32_t offA = (((uint32_t)ks * 32) + koffA) ^ xr16;
            const uint32_t offB = (((uint32_t)ks * 32) + koffB) ^ xr16;
            uint32_t ah[2][4], al[2][4], bh[4][4], bl[4][4];
#pragma unroll
            for (int i = 0; i < 2; i++) {
                ldm4(ah[i], Ah + baseA[i] + offA);
                ldm4(al[i], Al + baseA[i] + offA);
            }
#pragma unroll
            for (int j2 = 0; j2 < 4; j2++) {
                ldm4(bh[j2], Bh + baseB[j2] + offB);
                ldm4(bl[j2], Bl + baseB[j2] + offB);
            }
#pragma unroll
            for (int i = 0; i < 2; i++)
#pragma unroll
                for (int j = 0; j < 8; j++) {
                    const int j2 = j >> 1, sel = (j & 1) * 2;
                    mma16816(acc[i][j], ah[i], bh[j2][sel], bh[j2][sel + 1]);
                    mma16816(acc[i][j], ah[i], bl[j2][sel], bl[j2][sel + 1]);
                    mma16816(acc[i][j], al[i], bh[j2][sel], bh[j2][sel + 1]);
                }
        }
        __syncthreads();
    }

    const int mrow0 = mt + wm * 32 + (lane >> 2);
    const int qcol0 = q0 + wn * 64 + (lane & 3) * 2;
#pragma unroll
    for (int i = 0; i < 2; i++) {
#pragma unroll
        for (int j = 0; j < 8; j++) {
            const int q  = qcol0 + j * 8;
            const float bx = bias_s[q - q0], by = bias_s[q - q0 + 1];
#pragma unroll
            for (int half = 0; half < 2; half++) {
                const int m  = mrow0 + i * 16 + half * 8;
                const int bb = m & 63, tt = m >> 6;
                float2 v;
                v.x = acc[i][j][half * 2 + 0] + bx;
                v.y = acc[i][j][half * 2 + 1] + by;
                *reinterpret_cast<float2*>(
                    g_Z + (((size_t)dir * 512 + tt) * 64 + bb) * 1024 + q) = v;
            }
        }
    }
}

// ---------------------------------------------------------------------------
// Recurrence v4 — tensor-core (mma.sync bf16 split-3), no split-k.
// 128 CTAs = 2 dirs x 8 batch-groups x 8 cluster ranks (cluster of 8).
// Per CTA per step: C[16m, 128n] = A[16,256] @ B[256,128], A rows 0-7 = h
// (hi/lo bf16, converted each step), rows 8-15 = 0; B = Wr slice hi/lo bf16
// resident in SMEM (SW128-swizzled, K-major rows of 512B).
// Warp w owns n-cols [16w, 16w+16): 16 k-tiles x (2 subtiles x 3 split) mma.
// Gates assembled via lane-pair shfl; h broadcast via DSMEM + barrier.cluster.
// SMEM: Whi 64K | Wlo 64K | Ahi 8K | Alo 8K | h_f 2x8x260 f32 | mask 4K.
// ---------------------------------------------------------------------------
#define RV4_WHI   0
#define RV4_WLO   65536
#define RV4_AHI   131072
#define RV4_ALO   139264
#define RV4_HF    147456
#define RV4_MASK  (RV4_HF + 2 * 8 * 260 * 4)   // 164096
#define RV4_SMEM  (RV4_MASK + 4096)            // 168192

__device__ __forceinline__ uint32_t swz512(uint32_t row, uint32_t kb)
{
    // row stride 512B, SW128 within each 128B chunk; kb multiple of 2.
    return row * 512 + (kb & 0x180u) + (((kb & 0x70u) ^ ((row & 7u) << 4))) + (kb & 0xFu);
}

__global__ void __cluster_dims__(8, 1, 1) __launch_bounds__(256, 1)
lstm_rec_kernel(const float* __restrict__ Wr_f, const float* __restrict__ Wr_b,
                float* __restrict__ out)
{
    extern __shared__ char smr[];
    const uint32_t sbase = smem_u32(smr);
    float* h_f = reinterpret_cast<float*>(smr + RV4_HF);    // [2][8 b][260] (k=ug)
    unsigned char* m_s = reinterpret_cast<unsigned char*>(smr + RV4_MASK);

    const int tid  = threadIdx.x;
    const int bx   = blockIdx.x;
    const int dir  = bx >> 6;
    const int rank = bx & 7;
    const int bg   = (bx & 63) >> 3;
    const int w    = tid >> 5, lane = tid & 31;
    const int b    = lane >> 2;                 // batch row 0..7
    const int q    = lane & 3;
    const int mg   = lane >> 3, lr = lane & 7;  // ldmatrix groups

    // Per-lane owned (b, u) after gate shuffle:
    const int u_l  = 4 * w + (q >> 1) + 2 * (q & 1);
    const int ug   = (rank << 5) + u_l;
    const int b_global = (bg << 3) + b;

    // --- init: Wr slice -> bf16 hi/lo SMEM (one-time) ---------------------
    const float* Wr = dir ? Wr_b : Wr_f;
    for (int i = tid; i < 32768; i += 256) {
        const int n = i & 127;                  // n = u_local*4 + gate
        const int k = i >> 7;
        const float v = __ldg(&Wr[k * 1024 + (n & 3) * 256 + (rank << 5) + (n >> 2)]);
        __nv_bfloat16 hi, lo;
        split_bf16(v, hi, lo);
        const uint32_t off = swz512((uint32_t)n, (uint32_t)(k * 2));
        *reinterpret_cast<__nv_bfloat16*>(smr + RV4_WHI + off) = hi;
        *reinterpret_cast<__nv_bfloat16*>(smr + RV4_WLO + off) = lo;
    }
    // Zero A (hi+lo contiguous: 16 KB) — rows 8-15 stay zero forever
    for (int i = tid; i < 1024; i += 256)
        reinterpret_cast<float4*>(smr + RV4_AHI)[i] = make_float4(0.f, 0.f, 0.f, 0.f);
    for (int i = tid; i < 2 * 8 * 260; i += 256) h_f[i] = 0.f;
    for (int i = tid; i < 8 * 512; i += 256)
        m_s[i] = g_mask[((bg << 3) + (i >> 9)) * 512 + (i & 511)];

    // DSMEM broadcast addresses (both h buffers x 8 ranks)
    const uint32_t hf0 = sbase + RV4_HF + ((uint32_t)(b * 260 + ug) << 2);
    const uint32_t hf1 = hf0 + 8 * 260 * 4;
    uint32_t ra0[8], ra1[8];
#pragma unroll
    for (int r = 0; r < 8; r++) { ra0[r] = mapa_rank(hf0, r); ra1[r] = mapa_rank(hf1, r); }

    CLUSTER_SYNC();

    // ldmatrix address bases (constant over steps except k-tile offset)
    const uint32_t rowA = (uint32_t)(lr + (mg & 1) * 8);
    const uint32_t koffA = (uint32_t)((mg >> 1) * 16);
    const uint32_t rowB = (uint32_t)(w * 16 + lr + (mg >> 1) * 8);
    const uint32_t koffB = (uint32_t)((mg & 1) * 16);
    const uint32_t swA = (uint32_t)lr << 4;
    const uint32_t baseAhi = sbase + RV4_AHI + rowA * 512;
    const uint32_t baseAlo = sbase + RV4_ALO + rowA * 512;
    const uint32_t baseBhi = sbase + RV4_WHI + rowB * 512;
    const uint32_t baseBlo = sbase + RV4_WLO + rowB * 512;

    // Conversion-phase mapping: warp cb converts h row cb (b = warp id)
    const int cb = tid >> 5;
    const int ck = (tid & 31) * 8;              // 8 k values per thread
    const uint32_t convOff = swz512((uint32_t)cb, (uint32_t)(tid & 31) * 16);

    float cst = 0.f, hlast = 0.f;
    int cur = 0;

    const float4* Z4 = reinterpret_cast<const float4*>(g_Z);
    const int t0 = dir ? 511 : 0;
    float4 znext = __ldg(&Z4[(((size_t)dir * 512 + t0) * 64 + b_global) * 256 + ug]);

    for (int step = 0; step < 512; step++) {
        const int t = dir ? (511 - step) : step;
        const float4 zin = znext;
        if (step < 511) {
            const int tn = dir ? (510 - step) : (step + 1);
            znext = __ldg(&Z4[(((size_t)dir * 512 + tn) * 64 + b_global) * 256 + ug]);
        }

        // ---- convert h_f[cur] -> A smem (bf16 hi/lo, swizzled) ----------
        {
            const float* hr = h_f + (cur * 8 + cb) * 260 + ck;
            float4 p0 = *reinterpret_cast<const float4*>(hr);
            float4 p1 = *reinterpret_cast<const float4*>(hr + 4);
            __nv_bfloat16 h8[8], l8[8];
            split_bf16(p0.x, h8[0], l8[0]);
            split_bf16(p0.y, h8[1], l8[1]);
            split_bf16(p0.z, h8[2], l8[2]);
            split_bf16(p0.w, h8[3], l8[3]);
            split_bf16(p1.x, h8[4], l8[4]);
            split_bf16(p1.y, h8[5], l8[5]);
            split_bf16(p1.z, h8[6], l8[6]);
            split_bf16(p1.w, h8[7], l8[7]);
            *reinterpret_cast<uint4*>(smr + RV4_AHI + convOff) =
                *reinterpret_cast<uint4*>(h8);
            *reinterpret_cast<uint4*>(smr + RV4_ALO + convOff) =
                *reinterpret_cast<uint4*>(l8);
        }
        __syncthreads();

        // ---- tensor GEMM: C[16, 16 cols] for warp w ---------------------
        float acc0[4] = {0.f, 0.f, 0.f, 0.f};
        float acc1[4] = {0.f, 0.f, 0.f, 0.f};
#pragma unroll
        for (int kt = 0; kt < 16; kt++) {
            const uint32_t kbA = (uint32_t)kt * 32 + koffA;
            const uint32_t kbB = (uint32_t)kt * 32 + koffB;
            const uint32_t offA = (kbA & 0x180u) + ((kbA & 0x70u) ^ swA);
            const uint32_t offB = (kbB & 0x180u) + ((kbB & 0x70u) ^ swA);
            uint32_t ah[4], al[4], bh[4], bl[4];
            ldm4(ah, baseAhi + offA);
            ldm4(al, baseAlo + offA);
            ldm4(bh, baseBhi + offB);
            ldm4(bl, baseBlo + offB);
            mma16816(acc0, ah, bh[0], bh[1]);
            mma16816(acc0, ah, bl[0], bl[1]);
            mma16816(acc0, al, bh[0], bh[1]);
            mma16816(acc1, ah, bh[2], bh[3]);
            mma16816(acc1, ah, bl[2], bl[3]);
            mma16816(acc1, al, bh[2], bh[3]);
        }

        // ---- gate assembly: lane pair (q even/odd) exchange -------------
        // even q lanes hold (i,f) of u_a and u_b; odd q lanes hold (c,o).
        const bool odd = (q & 1) != 0;
        const float s0 = odd ? acc0[0] : acc1[0];
        const float s1 = odd ? acc0[1] : acc1[1];
        const float r0 = __shfl_xor_sync(0xffffffffu, s0, 1);
        const float r1 = __shfl_xor_sync(0xffffffffu, s1, 1);
        float zi = odd ? r0 : acc0[0];
        float zf = odd ? r1 : acc0[1];
        float zc = odd ? acc1[0] : r0;
        float zo = odd ? acc1[1] : r1;
        zi += zin.x; zf += zin.y; zc += zin.z; zo += zin.w;

        const float gi = tanhf(zi);
        const float gf = tanhf(zf);
        const float gc = tanhf(zc);
        const float go = tanhf(zo);
        const float cn = fmaf(gf, cst, gi * gc);
        const float hn = go * tanhf(cn);

        const bool  mk   = m_s[(b << 9) + t] != 0;
        const float hold = h_f[(cur * 8 + b) * 260 + ug];
        const float hv   = mk ? hn : hold;
        cst = mk ? cn : cst;

        out[((size_t)b_global * 512 + t) * 512 + (dir << 8) + ug] = hv;
        hlast = hv;

        // ---- broadcast h to all 8 CTAs' next buffer ---------------------
        const int nxt = cur ^ 1;
#pragma unroll
        for (int r = 0; r < 8; r++)
            st_cluster_f32(nxt ? ra1[r] : ra0[r], hv);

        CLUSTER_SYNC();
        cur = nxt;
    }

    out[16777216 + (size_t)b_global * 512 + (dir << 8) + ug] = hlast;
}

// ---------------------------------------------------------------------------
// Launch
// ---------------------------------------------------------------------------
extern "C" void kernel_launch(void* const* d_in, const int* in_sizes, int n_in,
                              void* d_out, int out_size)
{
    const float* x    = (const float*)d_in[0];
    const float* Wk_f = (const float*)d_in[1];
    const float* Wr_f = (const float*)d_in[2];
    const float* b_f  = (const float*)d_in[3];
    const float* Wk_b = (const float*)d_in[4];
    const float* Wr_b = (const float*)d_in[5];
    const float* b_b  = (const float*)d_in[6];
    float* out = (float*)d_out;

    mask_kernel<<<4096, 256>>>(x);
    convert_x_kernel<<<8192, 256>>>(x);
    convert_w_kernel<<<2048, 256>>>(Wk_f, Wk_b);

    cudaFuncSetAttribute(gemm_mma_kernel,
                         cudaFuncAttributeMaxDynamicSharedMemorySize, GEMM_SMEM_BYTES);
    dim3 gg(256, 16);
    gemm_mma_kernel<<<gg, 256, GEMM_SMEM_BYTES>>>(b_f, b_b);

    cudaFuncSetAttribute(lstm_rec_kernel,
                         cudaFuncAttributeMaxDynamicSharedMemorySize, RV4_SMEM);
    lstm_rec_kernel<<<128, 256, RV4_SMEM>>>(Wr_f, Wr_b, out);
}